// round 16
// baseline (speedup 1.0000x reference)
#include <cuda_runtime.h>
#include <cuda_fp16.h>
#include <math.h>

#define Bn    4
#define Sn    2048
#define Dn    1024
#define Hn    8
#define LRn   512
#define LRHn  64
#define SHDn  128
#define EXPn  2
#define Kn    4
#define CONVn 1042
#define NPROJ 1554
#define NPPAD 1664   // NPROJ padded to multiple of 128
#define BSn   8192   // B*S

typedef unsigned long long ull;
typedef unsigned int u32;

// ---------------- scratch (device globals; no runtime allocation) ----------------
__device__ float g_proj[BSn * NPROJ];
__device__ float g_xv[BSn * 1024];
__device__ float g_fv[BSn * 1024];
__device__ float g_scan[BSn * 1024];
__device__ float g_rin[BSn * Hn];
__device__ float g_cg[BSn * Hn];
__device__ int   g_prog[Bn];        // scan progress (per batch, 1 per 64-step chunk per head)
__device__ int   g_cchunk[Bn * 32]; // convbuild rows done per (batch, 64-chunk)
__device__ int   g_vchunk[Bn * 32]; // ugate rows done per (batch, 64-chunk)
// fp16 hi/lo operand splits
__device__ __align__(16) __half g_xh[BSn * Dn];
__device__ __align__(16) __half g_xl[BSn * Dn];
__device__ __align__(16) __half g_wh[NPPAD * Dn];
__device__ __align__(16) __half g_wl[NPPAD * Dn];
__device__ __align__(16) __half g_owh[Dn * LRn];
__device__ __align__(16) __half g_owl[Dn * LRn];
__device__ __align__(16) __half g_vh[BSn * LRn];
__device__ __align__(16) __half g_vl[BSn * LRn];

// ---------------- helpers ----------------
__device__ __forceinline__ float sigmoidf_(float x) {
    return __fdividef(1.f, 1.f + __expf(-x));
}
__device__ __forceinline__ float tanhf_(float x) {
    float t = __expf(-2.f * fabsf(x));
    float r = __fdividef(1.f - t, 1.f + t);
    return copysignf(r, x);
}
__device__ __forceinline__ float blk_sum256(float v, float* sbuf) {
    int lane = threadIdx.x & 31, wid = threadIdx.x >> 5;
#pragma unroll
    for (int off = 16; off; off >>= 1) v += __shfl_xor_sync(0xffffffffu, v, off);
    if (lane == 0) sbuf[wid] = v;
    __syncthreads();
    float tot = 0.f;
#pragma unroll
    for (int i = 0; i < 8; i++) tot += sbuf[i];
    __syncthreads();
    return tot;
}
__device__ __forceinline__ void cp_async16_s(u32 saddr, const void* gmem) {
    asm volatile("cp.async.cg.shared.global [%0], [%1], 16;\n" ::"r"(saddr), "l"(gmem));
}
__device__ __forceinline__ void spin_ge(volatile int* p, int target) {
    for (long it = 0; it < (1L << 27); it++) {
        if (*p >= target) break;
    }
}

// ---- packed fp32x2 ----
__device__ __forceinline__ ull ffma2(ull a, ull b, ull c) {
    ull d;
    asm("fma.rn.f32x2 %0, %1, %2, %3;" : "=l"(d) : "l"(a), "l"(b), "l"(c));
    return d;
}
__device__ __forceinline__ ull pk2(float x, float y) {
    ull r;
    asm("mov.b64 %0, {%1, %2};" : "=l"(r) : "f"(x), "f"(y));
    return r;
}
__device__ __forceinline__ float2 u2f(ull v) {
    float2 f;
    asm("mov.b64 {%0, %1}, %2;" : "=f"(f.x), "=f"(f.y) : "l"(v));
    return f;
}

// ---- fp16 mma m16n8k16 ----
__device__ __forceinline__ void mma_f16(float* d, const u32* a, const u32* b) {
    asm volatile(
        "mma.sync.aligned.m16n8k16.row.col.f32.f16.f16.f32 "
        "{%0,%1,%2,%3}, {%4,%5,%6,%7}, {%8,%9}, {%0,%1,%2,%3};"
        : "+f"(d[0]), "+f"(d[1]), "+f"(d[2]), "+f"(d[3])
        : "r"(a[0]), "r"(a[1]), "r"(a[2]), "r"(a[3]), "r"(b[0]), "r"(b[1]));
}

// ---------------- K0: all f32 -> fp16 hi/lo splits + counter reset ----------------
#define NX (BSn * Dn)
#define NW (NPPAD * Dn)
#define NO (Dn * LRn)
__global__ __launch_bounds__(256) void cvt_all_kernel(const float* __restrict__ x,
                                                      const float* __restrict__ w_in,
                                                      const float* __restrict__ out_w) {
    int i = blockIdx.x * 256 + threadIdx.x;
    if (i < Bn * 32) { g_cchunk[i] = 0; g_vchunk[i] = 0; }
    if (i < Bn) g_prog[i] = 0;
    if (i < NX) {
        float v = x[i];
        __half h = __float2half_rn(v);
        g_xh[i] = h;
        g_xl[i] = __float2half_rn(v - __half2float(h));
        return;
    }
    int j = i - NX;
    if (j < NW) {
        float v = (j < NPROJ * Dn) ? w_in[j] : 0.f;
        __half h = __float2half_rn(v);
        g_wh[j] = h;
        g_wl[j] = __float2half_rn(v - __half2float(h));
        return;
    }
    int k2 = j - NW;
    if (k2 < NO) {
        float v = out_w[k2];
        __half h = __float2half_rn(v);
        g_owh[k2] = h;
        g_owl[k2] = __float2half_rn(v - __half2float(h));
    }
}

// ---------------- fp16-split tensor-core GEMM tile (shared by K1 + mega K6 role) ----------------
#define TCM 128
#define TCN 128
#define TCKC 32
#define WROW 20
#define LVL_W (128 * WROW)
#define BUF_W (4 * LVL_W)
#define TC_SMEM_DYN (2 * BUF_W * 4) // 81920 bytes

__device__ __forceinline__ void gemm_tile_dev(const __half* __restrict__ Ah,
                                              const __half* __restrict__ Al,
                                              const __half* __restrict__ Bh,
                                              const __half* __restrict__ Bl,
                                              float* __restrict__ C,
                                              int M, int N, int Kd,
                                              int m0, int n0, u32* sm) {
    int tid = threadIdx.x;
    int wid = tid >> 5, lane = tid & 31;
    int g = lane >> 2, t = lane & 3;
    int wm = (wid >> 2) * 64, wn = (wid & 3) * 32;

    u32 sbase = (u32)__cvta_generic_to_shared(sm);

    const __half* srcA_h = Ah + (size_t)m0 * Kd;
    const __half* srcA_l = Al + (size_t)m0 * Kd;
    const __half* srcB_h = Bh + (size_t)n0 * Kd;
    const __half* srcB_l = Bl + (size_t)n0 * Kd;

    float acc[4][4][4];
#pragma unroll
    for (int i = 0; i < 4; i++)
#pragma unroll
        for (int j = 0; j < 4; j++)
#pragma unroll
            for (int q = 0; q < 4; q++) acc[i][j][q] = 0.f;

    int row2 = tid >> 2, j4 = tid & 3;
    const int nchunks = Kd / TCKC;

#define ISSUE_CHUNK(ck, buf) do {                                              \
        int k0_ = (ck) * TCKC;                                                 \
        u32 b_ = sbase + (buf) * BUF_W * 4;                                    \
        const __half* s0;                                                      \
        s0 = srcA_h + (size_t)row2 * Kd + k0_ + j4 * 8;                        \
        cp_async16_s(b_ + (0 * LVL_W + row2 * WROW + j4 * 4) * 4, s0);         \
        cp_async16_s(b_ + (0 * LVL_W + (row2 + 64) * WROW + j4 * 4) * 4,       \
                     s0 + (size_t)64 * Kd);                                    \
        s0 = srcA_l + (size_t)row2 * Kd + k0_ + j4 * 8;                        \
        cp_async16_s(b_ + (1 * LVL_W + row2 * WROW + j4 * 4) * 4, s0);         \
        cp_async16_s(b_ + (1 * LVL_W + (row2 + 64) * WROW + j4 * 4) * 4,       \
                     s0 + (size_t)64 * Kd);                                    \
        s0 = srcB_h + (size_t)row2 * Kd + k0_ + j4 * 8;                        \
        cp_async16_s(b_ + (2 * LVL_W + row2 * WROW + j4 * 4) * 4, s0);         \
        cp_async16_s(b_ + (2 * LVL_W + (row2 + 64) * WROW + j4 * 4) * 4,       \
                     s0 + (size_t)64 * Kd);                                    \
        s0 = srcB_l + (size_t)row2 * Kd + k0_ + j4 * 8;                        \
        cp_async16_s(b_ + (3 * LVL_W + row2 * WROW + j4 * 4) * 4, s0);         \
        cp_async16_s(b_ + (3 * LVL_W + (row2 + 64) * WROW + j4 * 4) * 4,       \
                     s0 + (size_t)64 * Kd);                                    \
        asm volatile("cp.async.commit_group;");                                \
    } while (0)

    ISSUE_CHUNK(0, 0);

    for (int ck = 0; ck < nchunks; ck++) {
        int cur = ck & 1;
        bool has_next = (ck + 1 < nchunks);
        if (has_next) {
            ISSUE_CHUNK(ck + 1, cur ^ 1);
            asm volatile("cp.async.wait_group 1;");
        } else {
            asm volatile("cp.async.wait_group 0;");
        }
        __syncthreads();

        const u32* SAh = sm + cur * BUF_W;
        const u32* SAl = SAh + LVL_W;
        const u32* SBh = SAh + 2 * LVL_W;
        const u32* SBl = SAh + 3 * LVL_W;

#pragma unroll
        for (int ks = 0; ks < 2; ks++) {
            int ko = ks * 8;
            u32 bh[4][2], bl[4][2];
#pragma unroll
            for (int nt = 0; nt < 4; nt++) {
                int rb = (wn + nt * 8 + g) * WROW + ko + t;
                bh[nt][0] = SBh[rb]; bh[nt][1] = SBh[rb + 4];
                bl[nt][0] = SBl[rb]; bl[nt][1] = SBl[rb + 4];
            }
#pragma unroll
            for (int mt = 0; mt < 4; mt++) {
                int r0 = (wm + mt * 16 + g) * WROW + ko + t;
                int r8 = r0 + 8 * WROW;
                u32 ah[4], al[4];
                ah[0] = SAh[r0]; ah[1] = SAh[r8];
                ah[2] = SAh[r0 + 4]; ah[3] = SAh[r8 + 4];
                al[0] = SAl[r0]; al[1] = SAl[r8];
                al[2] = SAl[r0 + 4]; al[3] = SAl[r8 + 4];
#pragma unroll
                for (int nt = 0; nt < 4; nt++) {
                    mma_f16(acc[mt][nt], ah, bh[nt]);   // hi*hi (exact in fp32)
                    mma_f16(acc[mt][nt], ah, bl[nt]);   // hi*lo
                    mma_f16(acc[mt][nt], al, bh[nt]);   // lo*hi
                }
            }
        }
        __syncthreads();
    }

#pragma unroll
    for (int mt = 0; mt < 4; mt++) {
#pragma unroll
        for (int nt = 0; nt < 4; nt++) {
            int r = m0 + wm + mt * 16 + g;
            int c = n0 + wn + nt * 8 + t * 2;
            if (c + 1 < N) {
                *(float2*)(C + (size_t)r * N + c) =
                    make_float2(acc[mt][nt][0], acc[mt][nt][1]);
                *(float2*)(C + (size_t)(r + 8) * N + c) =
                    make_float2(acc[mt][nt][2], acc[mt][nt][3]);
            } else if (c < N) {
                C[(size_t)r * N + c] = acc[mt][nt][0];
                C[(size_t)(r + 8) * N + c] = acc[mt][nt][2];
            }
        }
    }
}

__global__ __launch_bounds__(256) void h2s_gemm_nt(const __half* __restrict__ Ah,
                                                   const __half* __restrict__ Al,
                                                   const __half* __restrict__ Bh,
                                                   const __half* __restrict__ Bl,
                                                   float* __restrict__ C,
                                                   int M, int N, int Kd) {
    extern __shared__ u32 sm[];
    gemm_tile_dev(Ah, Al, Bh, Bl, C, M, N, Kd,
                  blockIdx.y * TCM, blockIdx.x * TCN, sm);
}

// ---------------- smem overlays for mega roles ----------------
struct ScanSmem {
    float h_sh[2][128];
    float rh_sh[128];
    float rin_s[Sn];
    float cg_s[Sn];
    float sbuf[8];
};
struct UgateSmem {
    float srow[1024];
    float suw[64 * 129];
    float sbuf[8];
};
struct ConvSmem {
    float sy[CONVn];
    float sb1[8], sb2[8];
    float srs[1];
};

// ---------------- mega kernel ----------------
// roles by blockIdx.x:
//   [0,32)          scan (1 CTA per (b,h))
//   [32,8224)       convbuild rows, s-major:   b=rid&3, s=rid>>2
//   [8224,16416)    ugate rows,    s-major:    b=rid&3, s=rid>>2
//   [16416,16928)   K6 gemm tiles: n0=(t&7)*128, m0=(t>>3)*128
#define CB_BASE 32
#define UG_BASE 8224
#define K6_BASE 16416
#define MEGA_GRID (K6_BASE + 512)

__global__ __launch_bounds__(256) void mega_kernel(const float* __restrict__ state_w,
                                                   const float* __restrict__ res_w,
                                                   const float* __restrict__ up_w,
                                                   const float* __restrict__ w_g_norm,
                                                   const float* __restrict__ conv_w,
                                                   const float* __restrict__ w_in_norm,
                                                   const float* __restrict__ w_f_norm,
                                                   const float* __restrict__ w_r_norm,
                                                   float* __restrict__ out) {
    extern __shared__ __align__(16) char dynsm[];
    int tid = threadIdx.x;
    int bid = blockIdx.x;

    if (bid < CB_BASE) {
        // ================= SCAN role =================
        ScanSmem* S = (ScanSmem*)dynsm;
        int b = bid >> 3, hh = bid & 7;
        int e = tid >> 1, half = tid & 1;

        const float* bw = state_w + (size_t)hh * 16384 + half * 64 * 128 + e;
        const float* bf = state_w + (size_t)(8 + hh) * 16384 + half * 64 * 128 + e;
        const float* br = state_w + (size_t)(16 + hh) * 16384 + half * 64 * 128 + e;
        float ssW = 0.f, ssF = 0.f, ssR = 0.f;
#pragma unroll 8
        for (int i = 0; i < 64; i++) {
            float vw = bw[i * 128], vf = bf[i * 128], vr = br[i * 128];
            ssW += vw * vw; ssF += vf * vf; ssR += vr * vr;
        }
        float totW = blk_sum256(ssW, S->sbuf);
        float totF = blk_sum256(ssF, S->sbuf);
        float totR = blk_sum256(ssR, S->sbuf);
        float invW = 1.f / fmaxf(sqrtf(totW), 1e-12f);
        float invF = 1.f / fmaxf(sqrtf(totF), 1e-12f);
        float invR = 1.f / fmaxf(sqrtf(totR), 1e-12f);

        ull W2[32], F2[32], R2[32];
#pragma unroll
        for (int i = 0; i < 32; i++) {
            W2[i] = pk2(bw[(2 * i) * 128] * invW, bw[(2 * i + 1) * 128] * invW);
            F2[i] = pk2(bf[(2 * i) * 128] * invF, bf[(2 * i + 1) * 128] * invF);
            R2[i] = pk2(br[(2 * i) * 128] * invR, br[(2 * i + 1) * 128] * invR);
        }

        if (tid < 128) S->h_sh[0][tid] = 0.f;
        float resw = res_w[hh];
        size_t rowbase = ((size_t)b * Sn) * 1024 + hh * 128;
        const float* xsrc = g_xv + rowbase + e;
        const float* fsrc = g_fv + rowbase + e;

        float xq[8], fq[8];

        for (int c = 0; c < 32; c++) {
            // wait for convbuild chunks c and c+1 of this batch
            if (tid == 0) {
                spin_ge(&g_cchunk[b * 32 + c], 64);
                if (c + 1 < 32) spin_ge(&g_cchunk[b * 32 + c + 1], 64);
            }
            __syncthreads();
            // load rin/cg for this chunk (ordered by the step-loop S1 barrier)
            {
                int t0 = c * 64;
                if (tid < 64)
                    S->rin_s[t0 + tid] = g_rin[(size_t)(b * Sn + t0 + tid) * 8 + hh];
                else if (tid < 128)
                    S->cg_s[t0 + tid - 64] = g_cg[(size_t)(b * Sn + t0 + tid - 64) * 8 + hh];
            }
            if (c == 0) {
#pragma unroll
                for (int s = 0; s < 8; s++) {
                    xq[s] = xsrc[(size_t)s * 1024];
                    fq[s] = fsrc[(size_t)s * 1024];
                }
            }

            for (int t8 = 0; t8 < 8; t8++) {
#pragma unroll
                for (int s = 0; s < 8; s++) {
                    int t = c * 64 + t8 * 8 + s;
                    int cur = t & 1, nxt = cur ^ 1;
                    __syncthreads();   // S1

                    const ulonglong2* h4 = (const ulonglong2*)(S->h_sh[cur]) + half * 8;
                    ull pRa = 0ull, pRb = 0ull;
#pragma unroll
                    for (int i = 0; i < 8; i++) {
                        ulonglong2 hv = h4[i];
                        pRa = ffma2(hv.x, R2[2 * i], pRa);
                        pRb = ffma2(hv.y, R2[2 * i + 1], pRb);
                    }
                    float2 fa = u2f(pRa), fb = u2f(pRb);
                    float pR = (fa.x + fa.y) + (fb.x + fb.y);
                    pR += __shfl_xor_sync(0xffffffffu, pR, 1);

                    float hcur_e = S->h_sh[cur][e];
                    if (half == 0) {
                        S->rh_sh[e] = sigmoidf_(S->rin_s[t] + pR) * hcur_e;
                    }
                    __syncthreads();   // S2

                    float xt = xq[s], ft = fq[s];
                    {
                        int tp = t + 8;
                        if (tp < Sn) {
                            xq[s] = xsrc[(size_t)tp * 1024];
                            fq[s] = fsrc[(size_t)tp * 1024];
                        }
                    }

                    const ulonglong2* rh4 = (const ulonglong2*)(S->rh_sh) + half * 8;
                    ull pFa = 0ull, pFb = 0ull, pWa = 0ull, pWb = 0ull;
#pragma unroll
                    for (int i = 0; i < 8; i++) {
                        ulonglong2 hv = h4[i];
                        ulonglong2 rv = rh4[i];
                        pWa = ffma2(rv.x, W2[2 * i], pWa);
                        pFa = ffma2(hv.x, F2[2 * i], pFa);
                        pWb = ffma2(rv.y, W2[2 * i + 1], pWb);
                        pFb = ffma2(hv.y, F2[2 * i + 1], pFb);
                    }
                    float2 wa = u2f(pWa), wb = u2f(pWb), ga = u2f(pFa), gb = u2f(pFb);
                    float pW = (wa.x + wa.y) + (wb.x + wb.y);
                    float pF = (ga.x + ga.y) + (gb.x + gb.y);
                    pW += __shfl_xor_sync(0xffffffffu, pW, 1);
                    pF += __shfl_xor_sync(0xffffffffu, pF, 1);

                    float hn = 0.f;
                    if (half == 1) {
                        float fgate = sigmoidf_(ft + pF);
                        float htl = tanhf_(xt + pW);
                        hn = fgate * hcur_e + (1.f - fgate) * htl;
                        S->h_sh[nxt][e] = hn;
                    }
                    float hn_b = __shfl_xor_sync(0xffffffffu, hn, 1);
                    if (half == 0) {
                        g_scan[rowbase + (size_t)t * 1024 + e] = resw * xt + hn_b * S->cg_s[t];
                    }
                }
            }
            // publish this 64-step chunk to ugate
            __threadfence();
            __syncthreads();
            if (tid == 0) atomicAdd(&g_prog[b], 1);
        }
    } else if (bid < UG_BASE) {
        // ================= CONVBUILD role =================
        ConvSmem* Cv = (ConvSmem*)dynsm;
        int rid = bid - CB_BASE;
        int b = rid & 3, s = rid >> 2;
        int row = b * Sn + s;

        const float* p0 = g_proj + (size_t)row * NPROJ;
        for (int c = tid; c < CONVn; c += 256) {
            float w0 = conv_w[c * 4 + 0], w1 = conv_w[c * 4 + 1];
            float w2 = conv_w[c * 4 + 2], w3 = conv_w[c * 4 + 3];
            float acc = w3 * p0[c];
            if (s >= 1) acc += w2 * p0[c - NPROJ];
            if (s >= 2) acc += w1 * p0[c - 2 * NPROJ];
            if (s >= 3) acc += w0 * p0[c - 3 * NPROJ];
            Cv->sy[c] = acc * sigmoidf_(acc);
        }
        __syncthreads();

        float s1 = 0.f, s2 = 0.f;
        for (int i = tid; i < 512; i += 256) {
            s1 += Cv->sy[i] * Cv->sy[i];
            s2 += Cv->sy[512 + i] * Cv->sy[512 + i];
        }
        float t1 = blk_sum256(s1, Cv->sb1);
        float t2 = blk_sum256(s2, Cv->sb2);
        if (tid == 0) {
            float sr = 0.f;
#pragma unroll
            for (int h = 0; h < 8; h++) sr += Cv->sy[1024 + h] * Cv->sy[1024 + h];
            Cv->srs[0] = rsqrtf(sr * (1.f / 8.f) + 1e-6f);
        }
        float si = rsqrtf(t1 * (1.f / 512.f) + 1e-6f);
        float sf = rsqrtf(t2 * (1.f / 512.f) + 1e-6f);
        __syncthreads();

        float e0 = Cv->sy[1040], e1 = Cv->sy[1041];
        float* xv = g_xv + (size_t)row * 1024;
        float* fv = g_fv + (size_t)row * 1024;
#pragma unroll
        for (int q = 0; q < 4; q++) {
            int o = tid + q * 256;
            int hh = o >> 7, rem = o & 127, ee = rem >> 6, dd = rem & 63;
            int ii = hh * 64 + dd;
            float ex = (ee == 0) ? e0 : e1;
            xv[o] = Cv->sy[ii] * si * w_in_norm[ii] * ex;
            fv[o] = Cv->sy[512 + ii] * sf * w_f_norm[ii] * ex;
        }
        if (tid < 8) {
            g_rin[(size_t)row * 8 + tid] = Cv->sy[1024 + tid] * Cv->srs[0] * w_r_norm[tid];
            g_cg[(size_t)row * 8 + tid] = Cv->sy[1032 + tid];
        }
        // publish
        __threadfence();
        __syncthreads();
        if (tid == 0) atomicAdd(&g_cchunk[b * 32 + (s >> 6)], 1);
    } else if (bid < K6_BASE) {
        // ================= UGATE role =================
        UgateSmem* U = (UgateSmem*)dynsm;
        int rid = bid - UG_BASE;
        int b = rid & 3, s = rid >> 2;
        int row = b * Sn + s;

        for (int i = tid; i < 8192; i += 256) {
            int j = i >> 7, d = i & 127;
            U->suw[j * 129 + d] = up_w[i];
        }
        if (tid == 0) {
            spin_ge(&g_prog[b], 8 * ((s >> 6) + 1));
        }
        __syncthreads();

        const float* sr = g_scan + (size_t)row * 1024;
        for (int i = tid; i < 1024; i += 256) U->srow[i] = __ldcg(sr + i);
        __syncthreads();

        int o0 = tid * 2, o1 = o0 + 1;
        int hhd = o0 >> 6;
        int j0 = o0 & 63, j1 = o1 & 63;
        const float* a = U->srow + hhd * 128;
        float acc0 = 0.f, acc1 = 0.f;
#pragma unroll 16
        for (int d = 0; d < 128; d++) {
            float av = a[d];
            acc0 += av * U->suw[j0 * 129 + d];
            acc1 += av * U->suw[j1 * 129 + d];
        }
        const float* gptr = g_proj + (size_t)row * NPROJ + CONVn;
        float gA = gptr[o0], gB = gptr[o1];
        float u0 = acc0 * (gA * sigmoidf_(gA));
        float u1 = acc1 * (gB * sigmoidf_(gB));

        float tot = blk_sum256(u0 * u0 + u1 * u1, U->sbuf);
        float scale = rsqrtf(tot * (1.f / 512.f) + 1e-6f);
        float v0 = u0 * scale * w_g_norm[o0];
        float v1 = u1 * scale * w_g_norm[o1];

        size_t ob = (size_t)row * 512;
        __half h0 = __float2half_rn(v0), h1 = __float2half_rn(v1);
        g_vh[ob + o0] = h0;
        g_vh[ob + o1] = h1;
        g_vl[ob + o0] = __float2half_rn(v0 - __half2float(h0));
        g_vl[ob + o1] = __float2half_rn(v1 - __half2float(h1));
        // publish
        __threadfence();
        __syncthreads();
        if (tid == 0) atomicAdd(&g_vchunk[b * 32 + (s >> 6)], 1);
    } else {
        // ================= K6 GEMM role =================
        int tix = bid - K6_BASE;            // 0..511
        int n0 = (tix & 7) * TCN;
        int m0 = (tix >> 3) * TCM;
        int b = m0 >> 11;                   // m0 / 2048
        int ch = (m0 & 2047) >> 6;          // starting 64-chunk (even)
        if (tid == 0) {
            spin_ge(&g_vchunk[b * 32 + ch], 64);
            spin_ge(&g_vchunk[b * 32 + ch + 1], 64);
        }
        __syncthreads();
        gemm_tile_dev(g_vh, g_vl, g_owh, g_owl, out, BSn, Dn, LRn, m0, n0, (u32*)dynsm);
    }
}

// ---------------- launch ----------------
extern "C" void kernel_launch(void* const* d_in, const int* in_sizes, int n_in,
                              void* d_out, int out_size) {
    const float* x         = (const float*)d_in[0];
    const float* w_in      = (const float*)d_in[1];
    const float* conv_w    = (const float*)d_in[2];
    const float* state_w   = (const float*)d_in[3];
    const float* up_w      = (const float*)d_in[4];
    const float* out_w     = (const float*)d_in[5];
    const float* res_w     = (const float*)d_in[6];
    const float* w_in_norm = (const float*)d_in[7];
    const float* w_f_norm  = (const float*)d_in[8];
    const float* w_r_norm  = (const float*)d_in[9];
    const float* w_g_norm  = (const float*)d_in[10];
    float* out = (float*)d_out;

    float* p_proj = nullptr;
    cudaGetSymbolAddress((void**)&p_proj, g_proj);
    __half *p_xh, *p_xl, *p_wh, *p_wl;
    cudaGetSymbolAddress((void**)&p_xh, g_xh);
    cudaGetSymbolAddress((void**)&p_xl, g_xl);
    cudaGetSymbolAddress((void**)&p_wh, g_wh);
    cudaGetSymbolAddress((void**)&p_wl, g_wl);

    cudaFuncSetAttribute(h2s_gemm_nt, cudaFuncAttributeMaxDynamicSharedMemorySize,
                         TC_SMEM_DYN);
    cudaFuncSetAttribute(mega_kernel, cudaFuncAttributeMaxDynamicSharedMemorySize,
                         TC_SMEM_DYN);

    // #1: operand splits + counter reset
    cvt_all_kernel<<<(NX + NW + NO + 255) / 256, 256>>>(x, w_in, out_w);
    // #2: proj = x @ w_in^T
    h2s_gemm_nt<<<dim3(NPPAD / TCN, BSn / TCM), 256, TC_SMEM_DYN>>>(
        p_xh, p_xl, p_wh, p_wl, p_proj, BSn, NPROJ, Dn);
    // #3: mega — convbuild + scan + ugate + K6, fully overlapped
    mega_kernel<<<MEGA_GRID, 256, TC_SMEM_DYN>>>(
        state_w, res_w, up_w, w_g_norm, conv_w, w_in_norm, w_f_norm, w_r_norm, out);
}